// round 5
// baseline (speedup 1.0000x reference)
#include <cuda_runtime.h>
#include <cuda_bf16.h>
#include <math.h>

// ---------------------------------------------------------------------------
// ConsistencyLoss: kl = mean_i sum_j t[idx_i]_j * (log t[idx_i]_j - log(softmax(x_i)_j + eps))
// With sum_j t_j == 1 (true for every table row after +eps renorm):
//   KL_i = C[idx] - dot(t[idx], x_i) + m_i + log(sum_j exp(x_ij - m_i))
// where C[idx] = sum_j t_j log t_j.  (eps inside log(p+eps) contributes ~1e-7
// absolute on KL~1 -> far below the 1e-3 threshold.)
//
// NOTE: JAX with default x64-disabled config downcasts int64 -> int32, so
// fatigue_targets arrives as an int32 buffer of B elements.
// ---------------------------------------------------------------------------

#define NBLOCKS 2368          // 148 SMs * 16 blocks
#define NTHREADS 256

__device__ float d_tab[4 * 8];   // normalized target rows, padded stride 8
__device__ float d_C[4];         // sum t log t per row
__device__ float d_partials[NBLOCKS];

// ---- setup: replicate reference fp32 arithmetic for the 4-row LUT ----------
__global__ void kl_setup_kernel() {
    const float table[4][7] = {
        {0.05f, 0.02f, 0.03f, 0.4f, 0.05f, 0.4f, 0.05f},
        {0.05f, 0.05f, 0.05f, 0.05f, 0.3f, 0.05f, 0.45f},
        {0.1f, 0.15f, 0.2f, 0.02f, 0.35f, 0.03f, 0.15f},
        {1.0f/7.0f, 1.0f/7.0f, 1.0f/7.0f, 1.0f/7.0f, 1.0f/7.0f, 1.0f/7.0f, 1.0f/7.0f},
    };
    if (threadIdx.x == 0 && blockIdx.x == 0) {
        const float eps = 1e-8f;
        for (int r = 0; r < 4; ++r) {
            float s = 0.f;
            #pragma unroll
            for (int j = 0; j < 7; ++j) s += table[r][j] + eps;
            float C = 0.f;
            #pragma unroll
            for (int j = 0; j < 7; ++j) {
                float t = (table[r][j] + eps) / s;
                d_tab[r * 8 + j] = t;
                C += t * logf(t);
            }
            d_tab[r * 8 + 7] = 0.f;
            d_C[r] = C;
        }
    }
}

// ---- main: fused softmax + KL, deterministic per-block partials ------------
__global__ void __launch_bounds__(NTHREADS, 8)
kl_main_kernel(const float* __restrict__ x,   // [B,7] emotion logits
               const int* __restrict__ tgt,   // [B] fatigue targets (int32)
               int B) {
    float acc = 0.f;
    const int stride = gridDim.x * blockDim.x;

    #pragma unroll 4
    for (int i = blockIdx.x * blockDim.x + threadIdx.x; i < B; i += stride) {
        const float* row = x + (size_t)i * 7;
        float x0 = row[0], x1 = row[1], x2 = row[2], x3 = row[3];
        float x4 = row[4], x5 = row[5], x6 = row[6];
        int t = tgt[i];
        int idx = ((unsigned)t <= 2u) ? t : 3;

        float m = fmaxf(fmaxf(fmaxf(x0, x1), fmaxf(x2, x3)),
                        fmaxf(fmaxf(x4, x5), x6));
        float s = __expf(x0 - m) + __expf(x1 - m) + __expf(x2 - m) +
                  __expf(x3 - m) + __expf(x4 - m) + __expf(x5 - m) +
                  __expf(x6 - m);
        float lz = __logf(s);

        const float* tp = &d_tab[idx * 8];
        float dot = tp[0] * x0;
        dot = fmaf(tp[1], x1, dot);
        dot = fmaf(tp[2], x2, dot);
        dot = fmaf(tp[3], x3, dot);
        dot = fmaf(tp[4], x4, dot);
        dot = fmaf(tp[5], x5, dot);
        dot = fmaf(tp[6], x6, dot);

        acc += d_C[idx] + m + lz - dot;
    }

    // deterministic block reduction: warp shuffle tree + smem tree
    __shared__ float warp_sums[NTHREADS / 32];
    #pragma unroll
    for (int off = 16; off > 0; off >>= 1)
        acc += __shfl_down_sync(0xFFFFFFFFu, acc, off);
    int lane = threadIdx.x & 31;
    int wid  = threadIdx.x >> 5;
    if (lane == 0) warp_sums[wid] = acc;
    __syncthreads();
    if (wid == 0) {
        float v = (lane < NTHREADS / 32) ? warp_sums[lane] : 0.f;
        #pragma unroll
        for (int off = 4; off > 0; off >>= 1)
            v += __shfl_down_sync(0xFFFFFFFFu, v, off);
        if (lane == 0) d_partials[blockIdx.x] = v;
    }
}

// ---- final: single-block deterministic double-precision sum ----------------
__global__ void kl_final_kernel(float* __restrict__ out, int nparts, int B) {
    __shared__ double sh[NTHREADS];
    double s = 0.0;
    for (int i = threadIdx.x; i < nparts; i += NTHREADS)
        s += (double)d_partials[i];
    sh[threadIdx.x] = s;
    __syncthreads();
    #pragma unroll
    for (int off = NTHREADS / 2; off > 0; off >>= 1) {
        if (threadIdx.x < off) sh[threadIdx.x] += sh[threadIdx.x + off];
        __syncthreads();
    }
    if (threadIdx.x == 0)
        out[0] = (float)(sh[0] / (double)B);
}

extern "C" void kernel_launch(void* const* d_in, const int* in_sizes, int n_in,
                              void* d_out, int out_size) {
    // Assign pointers BY SIZE, not by slot, to be robust to metadata ordering:
    //   emotion_logits: 7*B elements (largest)
    //   fatigue_logits: 3*B elements (unused)
    //   fatigue_targets: B elements (smallest)
    int big = 0, small = 0;
    for (int i = 1; i < n_in; ++i) {
        if (in_sizes[i] > in_sizes[big])   big = i;
        if (in_sizes[i] < in_sizes[small]) small = i;
    }
    const float* emotion  = (const float*)d_in[big];
    const int*   targets  = (const int*)d_in[small];
    int B = in_sizes[small];
    float* out = (float*)d_out;

    kl_setup_kernel<<<1, 32>>>();
    kl_main_kernel<<<NBLOCKS, NTHREADS>>>(emotion, targets, B);
    kl_final_kernel<<<1, NTHREADS>>>(out, NBLOCKS, B);
}